// round 2
// baseline (speedup 1.0000x reference)
#include <cuda_runtime.h>
#include <math.h>

#define H_ 128
#define W_ 256
#define C_ 64
#define F_ 128
#define B_ 4
#define IH 130
#define IW 258

// Per-(h, tap) tables: y is fully determined by (h,tap); x = w + dx + off_x(h,tap).
__device__ int   g_y0t[H_ * 9];
__device__ int   g_y1t[H_ * 9];
__device__ float g_wyT[H_ * 9];   // (y1f - y)
__device__ float g_wyB[H_ * 9];   // (y - y0f)
__device__ float g_offx[H_ * 9];  // off added to x (the "y_r diff" per the original's swap)

__global__ void precompute_kernel() {
    int idx = blockIdx.x * blockDim.x + threadIdx.x;
    if (idx >= H_ * 9) return;
    int h = idx / 9, k = idx % 9;
    const double pi = 3.14159265358979323846;
    double unit_w = 2.0 * pi / (double)W_;
    double unit_h = pi / (2.0 * (double)H_);     // skydome
    double rho = tan(unit_w);                    // dilation = 1
    // theta = (xc - 0.5*w)*unit_w = 0 for W even -> p_u = (cos phi, sin phi, 0)
    double phi = ((double)H_ - (double)h) * unit_h;
    double cphi = cos(phi), sphi = sin(phi);
    // t_x = cross(v, p_u) = (0, 0, -cphi); t_y = cross(p_u, t_x) = (-sphi*cphi, cphi*cphi, 0)
    const int ra[9] = { 1, 1, 1, 0, 0, 0, -1, -1, -1 };
    const int rb[9] = { -1, 0, 1, -1, 0, 1, -1, 0, 1 };
    double a = (double)ra[k], b = (double)rb[k];
    double ux = cphi + rho * (b * (-sphi * cphi));
    double uy = sphi + rho * (b * (cphi * cphi));
    double uz = rho * (a * (-cphi));

    double bse = atan2(uz, ux);
    double theta_r;
    if (ux > 0.0)      theta_r = bse;
    else if (ux < 0.0) theta_r = (uz >= 0.0) ? (bse + pi) : (bse - pi);
    else               theta_r = (uz > 0.0) ? (0.5 * pi) : (-0.5 * pi);
    double phi_r = asin(uy);
    double x_r = (theta_r / pi + 1.0) * 0.5 * (double)W_;
    double y_r = (1.0 - 2.0 * phi_r / pi) * (double)H_;

    // center tap (a=0, b=0): ux=cphi, uy=sphi, uz=0
    double bse_c = atan2(0.0, cphi);
    double theta_c;
    if (cphi > 0.0)      theta_c = bse_c;
    else if (cphi < 0.0) theta_c = bse_c + pi;     // uz=0 >= 0
    else                 theta_c = -0.5 * pi;       // uz=0, not > 0
    double x_rc = (theta_c / pi + 1.0) * 0.5 * (double)W_;
    double y_rc = (1.0 - 2.0 * asin(sphi) / pi) * (double)H_;

    // off[...,0] (x_r diff) is added to y; off[...,1] (y_r diff) is added to x  (faithful to original)
    float off_to_y = (float)(x_r - x_rc);
    float off_to_x = (float)(y_r - y_rc);

    int dy = k / 3;
    // y path (constant over w, fold fully)
    float yf = (float)(h + dy) + off_to_y;                 // matches f32(base_y) + f32(off)
    yf = fminf(fmaxf(yf, 0.0f), (float)(IH - 1));
    int y0 = (int)floorf(yf);
    int y1 = y0 + 1;
    y0 = max(0, min(y0, IH - 1));
    y1 = max(0, min(y1, IH - 1));
    g_y0t[idx] = y0;
    g_y1t[idx] = y1;
    g_wyT[idx] = (float)y1 - yf;
    g_wyB[idx] = yf - (float)y0;
    g_offx[idx] = off_to_x;
}

// Tile: 64 pixels (fixed b,h; consecutive w) x 128 F, K looped over 9 taps of 64 channels.
__global__ __launch_bounds__(256) void distconv_kernel(
    const float* __restrict__ inp,   // [B,H,W,C]
    const float* __restrict__ wk,    // [576,128]
    const float* __restrict__ bias,  // [128]
    float* __restrict__ out)         // [B,H,W,F]
{
    __shared__ float As[64][64];     // [c][m], XOR-swizzled in m-groups of 4
    __shared__ float Bs[64][128];    // [c][f]

    const int b = blockIdx.z, h = blockIdx.y;
    const int w0 = blockIdx.x * 64;
    const int tid = threadIdx.x;

    // compute mapping: 16 threads over m (4 each), 16 over f (8 each)
    const int txm = tid & 15, ty = tid >> 4;
    const int m0 = txm << 2, f0 = ty << 3;
    // loader mapping: 64 pixels x 4 channel-quarters
    const int lp = tid >> 2, lq = tid & 3;
    const int wpix = w0 + lp;
    const float* inpB = inp + (size_t)b * (H_ * W_ * C_);

    float acc[4][8];
#pragma unroll
    for (int i = 0; i < 4; ++i)
#pragma unroll
        for (int j = 0; j < 8; ++j) acc[i][j] = 0.f;

    // store swizzle: physical m-group = (lp>>2) ^ (c>>4); c>>4 == lq for this thread
    const int pcol = ((((lp >> 2) ^ lq)) << 2) | (lp & 3);

    for (int k = 0; k < 9; ++k) {
        // ---- load B tile: weight rows [64k, 64k+64) ----
        {
            const float4* src = (const float4*)(wk + (size_t)(k * 64) * 128);
            float4* dst = (float4*)&Bs[0][0];
#pragma unroll
            for (int i = 0; i < 8; ++i) {
                int e = i * 256 + tid;
                dst[e] = src[e];
            }
        }
        // ---- gather + bilinear blend A tile ----
        {
            int t = h * 9 + k;
            float wyT = g_wyT[t], wyB = g_wyB[t];
            int y0 = g_y0t[t], y1 = g_y1t[t];
            int dxk = k - (k / 3) * 3;
            float x = (float)(wpix + dxk) + g_offx[t];   // matches f32(base_x) + f32(off)
            if (x < 0.f) x += (float)IW;
            if (x > (float)(IW - 1)) x -= (float)IW;
            int x0 = (int)floorf(x);
            int x1 = x0 + 1;
            x0 = max(0, min(x0, IW - 1));
            x1 = max(0, min(x1, IW - 1));
            float wxl = (float)x1 - x;
            float wxr = x - (float)x0;
            float w00 = wyT * wxl, w01 = wyT * wxr, w10 = wyB * wxl, w11 = wyB * wxr;
            bool vy0 = (y0 >= 1) && (y0 <= H_);
            bool vy1 = (y1 >= 1) && (y1 <= H_);
            bool vx0 = (x0 >= 1) && (x0 <= W_);
            bool vx1 = (x1 >= 1) && (x1 <= W_);
            const float* p00 = (vy0 && vx0) ? inpB + ((size_t)(y0 - 1) * W_ + (x0 - 1)) * C_ : (const float*)0;
            const float* p01 = (vy0 && vx1) ? inpB + ((size_t)(y0 - 1) * W_ + (x1 - 1)) * C_ : (const float*)0;
            const float* p10 = (vy1 && vx0) ? inpB + ((size_t)(y1 - 1) * W_ + (x0 - 1)) * C_ : (const float*)0;
            const float* p11 = (vy1 && vx1) ? inpB + ((size_t)(y1 - 1) * W_ + (x1 - 1)) * C_ : (const float*)0;
            int cb = lq << 4;
#pragma unroll
            for (int j = 0; j < 4; ++j) {
                int c = cb + (j << 2);
                float sx = 0.f, sy = 0.f, sz = 0.f, sw = 0.f;
                if (p00) { float4 v = *(const float4*)(p00 + c); sx += w00 * v.x; sy += w00 * v.y; sz += w00 * v.z; sw += w00 * v.w; }
                if (p01) { float4 v = *(const float4*)(p01 + c); sx += w01 * v.x; sy += w01 * v.y; sz += w01 * v.z; sw += w01 * v.w; }
                if (p10) { float4 v = *(const float4*)(p10 + c); sx += w10 * v.x; sy += w10 * v.y; sz += w10 * v.z; sw += w10 * v.w; }
                if (p11) { float4 v = *(const float4*)(p11 + c); sx += w11 * v.x; sy += w11 * v.y; sz += w11 * v.z; sw += w11 * v.w; }
                As[c + 0][pcol] = sx;
                As[c + 1][pcol] = sy;
                As[c + 2][pcol] = sz;
                As[c + 3][pcol] = sw;
            }
        }
        __syncthreads();
        // ---- inner product over this tap's 64 channels ----
#pragma unroll 16
        for (int c = 0; c < 64; ++c) {
            int pg = (txm ^ (c >> 4)) << 2;
            float4 av = *(const float4*)&As[c][pg];
            float4 b0 = *(const float4*)&Bs[c][f0];
            float4 b1 = *(const float4*)&Bs[c][f0 + 4];
            float am[4] = { av.x, av.y, av.z, av.w };
            float bn[8] = { b0.x, b0.y, b0.z, b0.w, b1.x, b1.y, b1.z, b1.w };
#pragma unroll
            for (int i = 0; i < 4; ++i)
#pragma unroll
                for (int j = 0; j < 8; ++j) acc[i][j] += am[i] * bn[j];
        }
        __syncthreads();
    }

    // ---- epilogue: bias + relu, store ----
    float bv[8];
#pragma unroll
    for (int j = 0; j < 8; ++j) bv[j] = bias[f0 + j];
#pragma unroll
    for (int i = 0; i < 4; ++i) {
        int m = m0 + i;
        size_t o = ((((size_t)b * H_ + h) * W_) + (size_t)(w0 + m)) * F_ + f0;
        float4 r0, r1;
        r0.x = fmaxf(acc[i][0] + bv[0], 0.f);
        r0.y = fmaxf(acc[i][1] + bv[1], 0.f);
        r0.z = fmaxf(acc[i][2] + bv[2], 0.f);
        r0.w = fmaxf(acc[i][3] + bv[3], 0.f);
        r1.x = fmaxf(acc[i][4] + bv[4], 0.f);
        r1.y = fmaxf(acc[i][5] + bv[5], 0.f);
        r1.z = fmaxf(acc[i][6] + bv[6], 0.f);
        r1.w = fmaxf(acc[i][7] + bv[7], 0.f);
        *(float4*)(out + o) = r0;
        *(float4*)(out + o + 4) = r1;
    }
}

extern "C" void kernel_launch(void* const* d_in, const int* in_sizes, int n_in,
                              void* d_out, int out_size) {
    (void)in_sizes; (void)n_in; (void)out_size;
    const float* inp  = (const float*)d_in[0];
    const float* wk   = (const float*)d_in[1];
    const float* bias = (const float*)d_in[2];
    float* out = (float*)d_out;

    precompute_kernel<<<(H_ * 9 + 127) / 128, 128>>>();
    dim3 grid(W_ / 64, H_, B_);
    distconv_kernel<<<grid, 256>>>(inp, wk, bias, out);
}

// round 4
// speedup vs baseline: 1.2590x; 1.2590x over previous
#include <cuda_runtime.h>
#include <cuda_bf16.h>
#include <math.h>
#include <stdint.h>

#define H_ 128
#define W_ 256
#define C_ 64
#define F_ 128
#define B_ 4
#define IH 130
#define IW 258

// ---------------- device scratch ----------------
__device__ int   g_y0t[H_ * 9];
__device__ int   g_y1t[H_ * 9];
__device__ float g_wyT[H_ * 9];
__device__ float g_wyB[H_ * 9];
__device__ float g_offx[H_ * 9];
// B fragments in mma.m16n8k16 register order: [tap][ks][n8][lane] -> uint2 {b0,b1}
__device__ uint2 g_bh[9 * 4 * 16 * 32];
__device__ uint2 g_bl[9 * 4 * 16 * 32];

// ---------------- helpers ----------------
__device__ __forceinline__ uint32_t smem_u32(const void* p) {
    uint32_t a;
    asm("{ .reg .u64 t; cvta.to.shared.u64 t, %1; cvt.u32.u64 %0, t; }" : "=r"(a) : "l"(p));
    return a;
}
__device__ __forceinline__ uint32_t cvt_bf16x2(float lo, float hi) {
    uint32_t r;
    asm("cvt.rn.bf16x2.f32 %0, %1, %2;" : "=r"(r) : "f"(hi), "f"(lo));
    return r;
}
__device__ __forceinline__ void ldsm_x4(uint32_t* r, uint32_t addr) {
    asm volatile("ldmatrix.sync.aligned.m8n8.x4.shared.b16 {%0,%1,%2,%3}, [%4];"
                 : "=r"(r[0]), "=r"(r[1]), "=r"(r[2]), "=r"(r[3]) : "r"(addr));
}
__device__ __forceinline__ void mma_bf16(float* d, const uint32_t* a, uint32_t b0, uint32_t b1) {
    asm volatile(
        "mma.sync.aligned.m16n8k16.row.col.f32.bf16.bf16.f32 "
        "{%0,%1,%2,%3}, {%4,%5,%6,%7}, {%8,%9}, {%0,%1,%2,%3};"
        : "+f"(d[0]), "+f"(d[1]), "+f"(d[2]), "+f"(d[3])
        : "r"(a[0]), "r"(a[1]), "r"(a[2]), "r"(a[3]), "r"(b0), "r"(b1));
}

// ---------------- precompute: distortion tables (faithful, fp64) ----------------
__global__ void precompute_kernel() {
    int idx = blockIdx.x * blockDim.x + threadIdx.x;
    if (idx >= H_ * 9) return;
    int h = idx / 9, k = idx % 9;
    const double pi = 3.14159265358979323846;
    double unit_w = 2.0 * pi / (double)W_;
    double unit_h = pi / (2.0 * (double)H_);
    double rho = tan(unit_w);
    double phi = ((double)H_ - (double)h) * unit_h;
    double cphi = cos(phi), sphi = sin(phi);
    const int ra[9] = { 1, 1, 1, 0, 0, 0, -1, -1, -1 };
    const int rb[9] = { -1, 0, 1, -1, 0, 1, -1, 0, 1 };
    double a = (double)ra[k], b = (double)rb[k];
    double ux = cphi + rho * (b * (-sphi * cphi));
    double uy = sphi + rho * (b * (cphi * cphi));
    double uz = rho * (a * (-cphi));

    double bse = atan2(uz, ux);
    double theta_r;
    if (ux > 0.0)      theta_r = bse;
    else if (ux < 0.0) theta_r = (uz >= 0.0) ? (bse + pi) : (bse - pi);
    else               theta_r = (uz > 0.0) ? (0.5 * pi) : (-0.5 * pi);
    double phi_r = asin(uy);
    double x_r = (theta_r / pi + 1.0) * 0.5 * (double)W_;
    double y_r = (1.0 - 2.0 * phi_r / pi) * (double)H_;

    double bse_c = atan2(0.0, cphi);
    double theta_c;
    if (cphi > 0.0)      theta_c = bse_c;
    else if (cphi < 0.0) theta_c = bse_c + pi;
    else                 theta_c = -0.5 * pi;
    double x_rc = (theta_c / pi + 1.0) * 0.5 * (double)W_;
    double y_rc = (1.0 - 2.0 * asin(sphi) / pi) * (double)H_;

    float off_to_y = (float)(x_r - x_rc);   // original's swap: x_r diff -> y
    float off_to_x = (float)(y_r - y_rc);

    int dy = k / 3;
    float yf = (float)(h + dy) + off_to_y;
    yf = fminf(fmaxf(yf, 0.0f), (float)(IH - 1));
    int y0 = (int)floorf(yf);
    int y1 = y0 + 1;
    y0 = max(0, min(y0, IH - 1));
    y1 = max(0, min(y1, IH - 1));
    g_y0t[idx] = y0;
    g_y1t[idx] = y1;
    g_wyT[idx] = (float)y1 - yf;
    g_wyB[idx] = yf - (float)y0;
    g_offx[idx] = off_to_x;
}

// ---------------- precompute: B fragments (hi/lo bf16, mma register order) ----------------
__global__ void bfrag_kernel(const float* __restrict__ wk) {
    int idx = blockIdx.x * blockDim.x + threadIdx.x;
    if (idx >= 9 * 4 * 16 * 32) return;
    int lane = idx & 31;
    int n8 = (idx >> 5) & 15;
    int ks = (idx >> 9) & 3;
    int tap = idx >> 11;
    int g = lane >> 2, tg = lane & 3;
    int n = n8 * 8 + g;
    int kb = ks * 16 + 2 * tg;
    float w0 = wk[(size_t)(tap * 64 + kb) * 128 + n];
    float w1 = wk[(size_t)(tap * 64 + kb + 1) * 128 + n];
    float w2 = wk[(size_t)(tap * 64 + kb + 8) * 128 + n];
    float w3 = wk[(size_t)(tap * 64 + kb + 9) * 128 + n];
    __nv_bfloat16 h0 = __float2bfloat16(w0), h1 = __float2bfloat16(w1);
    __nv_bfloat16 h2 = __float2bfloat16(w2), h3 = __float2bfloat16(w3);
    uint32_t bh0 = ((uint32_t)__bfloat16_as_ushort(h1) << 16) | __bfloat16_as_ushort(h0);
    uint32_t bh1 = ((uint32_t)__bfloat16_as_ushort(h3) << 16) | __bfloat16_as_ushort(h2);
    uint32_t bl0 = cvt_bf16x2(w0 - __bfloat162float(h0), w1 - __bfloat162float(h1));
    uint32_t bl1 = cvt_bf16x2(w2 - __bfloat162float(h2), w3 - __bfloat162float(h3));
    g_bh[idx] = make_uint2(bh0, bh1);
    g_bl[idx] = make_uint2(bl0, bl1);
}

// ---------------- main fused kernel ----------------
// CTA: 128 pixels x 128 F. 8 warps: warp_m (2) x warp_n (4); warp tile 64x32.
// Per tap: build A hi/lo (bilinear gather) into smem, then 4 k16-steps x 3 products.
__global__ __launch_bounds__(256, 2) void distconv_mma(
    const float* __restrict__ inp,
    const float* __restrict__ bias,
    float* __restrict__ out)
{
    __shared__ __align__(128) unsigned char sA_hi[16384];  // [m:128][8 chunks x16B], swizzled
    __shared__ __align__(128) unsigned char sA_lo[16384];

    const int tid = threadIdx.x;
    const int wid = tid >> 5, lane = tid & 31;
    const int warp_m = wid >> 2, warp_n = wid & 3;
    const int g = lane >> 2, tg = lane & 3;

    const int b = blockIdx.z, h = blockIdx.y;
    const int w0 = blockIdx.x * 128;
    const float* inpB = inp + (size_t)b * (H_ * W_ * C_);

    // gather mapping
    const int p = tid >> 1;
    const int halfc = (tid & 1) << 5;
    const int wpix = w0 + p;

    // ldmatrix addressing (A): row = warp_m*64 + mi*16 + (lane&15), khalf = lane>>4
    const uint32_t aHi = smem_u32(sA_hi), aLo = smem_u32(sA_lo);
    const uint32_t rowoff = (uint32_t)(warp_m * 64 + (lane & 15)) * 128;
    const int rlo = lane & 7;
    const int khalf = lane >> 4;

    float acc[4][4][4];
#pragma unroll
    for (int mi = 0; mi < 4; ++mi)
#pragma unroll
        for (int ni = 0; ni < 4; ++ni)
#pragma unroll
            for (int q = 0; q < 4; ++q) acc[mi][ni][q] = 0.f;

    for (int k = 0; k < 9; ++k) {
        if (k) __syncthreads();   // prior tap's ldmatrix done before overwrite
        // ---- A build: bilinear gather + bf16 hi/lo split ----
        {
            int t9 = h * 9 + k;
            float wyT = g_wyT[t9], wyB = g_wyB[t9];
            int y0 = g_y0t[t9], y1 = g_y1t[t9];
            int dxk = k - (k / 3) * 3;
            float x = (float)(wpix + dxk) + g_offx[t9];
            if (x < 0.f) x += (float)IW;
            if (x > (float)(IW - 1)) x -= (float)IW;
            int x0 = (int)floorf(x);
            int x1 = x0 + 1;
            x0 = max(0, min(x0, IW - 1));
            x1 = max(0, min(x1, IW - 1));
            float wxl = (float)x1 - x, wxr = x - (float)x0;
            float w00 = wyT * wxl, w01 = wyT * wxr, w10 = wyB * wxl, w11 = wyB * wxr;
            bool vy0 = (y0 >= 1) && (y0 <= H_);
            bool vy1 = (y1 >= 1) && (y1 <= H_);
            bool vx0 = (x0 >= 1) && (x0 <= W_);
            bool vx1 = (x1 >= 1) && (x1 <= W_);
            const float* p00 = (vy0 && vx0) ? inpB + ((size_t)(y0 - 1) * W_ + (x0 - 1)) * C_ : (const float*)0;
            const float* p01 = (vy0 && vx1) ? inpB + ((size_t)(y0 - 1) * W_ + (x1 - 1)) * C_ : (const float*)0;
            const float* p10 = (vy1 && vx0) ? inpB + ((size_t)(y1 - 1) * W_ + (x0 - 1)) * C_ : (const float*)0;
            const float* p11 = (vy1 && vx1) ? inpB + ((size_t)(y1 - 1) * W_ + (x1 - 1)) * C_ : (const float*)0;
#pragma unroll
            for (int j = 0; j < 8; ++j) {
                int c = halfc + (j << 2);
                float v0 = 0.f, v1 = 0.f, v2 = 0.f, v3 = 0.f;
                if (p00) { float4 q = *(const float4*)(p00 + c); v0 += w00 * q.x; v1 += w00 * q.y; v2 += w00 * q.z; v3 += w00 * q.w; }
                if (p01) { float4 q = *(const float4*)(p01 + c); v0 += w01 * q.x; v1 += w01 * q.y; v2 += w01 * q.z; v3 += w01 * q.w; }
                if (p10) { float4 q = *(const float4*)(p10 + c); v0 += w10 * q.x; v1 += w10 * q.y; v2 += w10 * q.z; v3 += w10 * q.w; }
                if (p11) { float4 q = *(const float4*)(p11 + c); v0 += w11 * q.x; v1 += w11 * q.y; v2 += w11 * q.z; v3 += w11 * q.w; }
                __nv_bfloat16 h0 = __float2bfloat16(v0), h1 = __float2bfloat16(v1);
                __nv_bfloat16 h2 = __float2bfloat16(v2), h3 = __float2bfloat16(v3);
                uint32_t hiA = ((uint32_t)__bfloat16_as_ushort(h1) << 16) | __bfloat16_as_ushort(h0);
                uint32_t hiB = ((uint32_t)__bfloat16_as_ushort(h3) << 16) | __bfloat16_as_ushort(h2);
                uint32_t loA = cvt_bf16x2(v0 - __bfloat162float(h0), v1 - __bfloat162float(h1));
                uint32_t loB = cvt_bf16x2(v2 - __bfloat162float(h2), v3 - __bfloat162float(h3));
                // swizzled store: chunk = c>>3, chunk' = chunk ^ (p&7), byte-in-chunk = (c&7)*2
                uint32_t addr = (uint32_t)p * 128 + ((uint32_t)((c >> 3) ^ (p & 7)) << 4) + (uint32_t)(c & 7) * 2;
                *(uint2*)(sA_hi + addr) = make_uint2(hiA, hiB);
                *(uint2*)(sA_lo + addr) = make_uint2(loA, loB);
            }
        }
        __syncthreads();

        // ---- MMA phase: 4 k16-steps ----
#pragma unroll
        for (int ks = 0; ks < 4; ++ks) {
            // B fragments from global (register order)
            uint2 BH[4], BL[4];
            int bidx = ((k * 4 + ks) * 16 + warp_n * 4) * 32 + lane;
#pragma unroll
            for (int ni = 0; ni < 4; ++ni) {
                BH[ni] = g_bh[bidx + ni * 32];
                BL[ni] = g_bl[bidx + ni * 32];
            }
            uint32_t swz = ((uint32_t)((ks * 2 + khalf) ^ rlo)) << 4;
            // A-hi fragments
            uint32_t AH[4][4];
#pragma unroll
            for (int mi = 0; mi < 4; ++mi)
                ldsm_x4(AH[mi], aHi + rowoff + (uint32_t)mi * 2048 + swz);
#pragma unroll
            for (int mi = 0; mi < 4; ++mi)
#pragma unroll
                for (int ni = 0; ni < 4; ++ni) {
                    mma_bf16(acc[mi][ni], AH[mi], BH[ni].x, BH[ni].y);
                    mma_bf16(acc[mi][ni], AH[mi], BL[ni].x, BL[ni].y);
                }
            // A-lo fragments
            uint32_t AL[4][4];
#pragma unroll
            for (int mi = 0; mi < 4; ++mi)
                ldsm_x4(AL[mi], aLo + rowoff + (uint32_t)mi * 2048 + swz);
#pragma unroll
            for (int mi = 0; mi < 4; ++mi)
#pragma unroll
                for (int ni = 0; ni < 4; ++ni)
                    mma_bf16(acc[mi][ni], AL[mi], BH[ni].x, BH[ni].y);
        }
    }

    // ---- epilogue: bias + relu, float2 stores ----
    float2 bv[4];
#pragma unroll
    for (int ni = 0; ni < 4; ++ni) {
        int f = warp_n * 32 + ni * 8 + 2 * tg;
        bv[ni] = *(const float2*)(bias + f);
    }
    size_t rowbase = (((size_t)b * H_ + h) * W_ + w0) * F_;
#pragma unroll
    for (int mi = 0; mi < 4; ++mi) {
        int mA = warp_m * 64 + mi * 16 + g;
#pragma unroll
        for (int ni = 0; ni < 4; ++ni) {
            int f = warp_n * 32 + ni * 8 + 2 * tg;
            float2 oA, oB;
            oA.x = fmaxf(acc[mi][ni][0] + bv[ni].x, 0.f);
            oA.y = fmaxf(acc[mi][ni][1] + bv[ni].y, 0.f);
            oB.x = fmaxf(acc[mi][ni][2] + bv[ni].x, 0.f);
            oB.y = fmaxf(acc[mi][ni][3] + bv[ni].y, 0.f);
            *(float2*)(out + rowbase + (size_t)mA * F_ + f) = oA;
            *(float2*)(out + rowbase + (size_t)(mA + 8) * F_ + f) = oB;
        }
    }
}

extern "C" void kernel_launch(void* const* d_in, const int* in_sizes, int n_in,
                              void* d_out, int out_size) {
    (void)in_sizes; (void)n_in; (void)out_size;
    const float* inp  = (const float*)d_in[0];
    const float* wk   = (const float*)d_in[1];
    const float* bias = (const float*)d_in[2];
    float* out = (float*)d_out;

    precompute_kernel<<<(H_ * 9 + 127) / 128, 128>>>();
    bfrag_kernel<<<(9 * 4 * 16 * 32 + 255) / 256, 256>>>(wk);
    dim3 grid(W_ / 128, H_, B_);
    distconv_mma<<<grid, 256>>>(inp, bias, out);
}

// round 6
// speedup vs baseline: 2.4069x; 1.9117x over previous
#include <cuda_runtime.h>
#include <cuda_bf16.h>
#include <math.h>
#include <stdint.h>

#define H_ 128
#define W_ 256
#define C_ 64
#define F_ 128
#define B_ 4
#define IH 130
#define IW 258

// ---------------- device scratch ----------------
__device__ int   g_y0t[H_ * 9];
__device__ int   g_y1t[H_ * 9];
__device__ float g_wyT[H_ * 9];
__device__ float g_wyB[H_ * 9];
__device__ float g_offx[H_ * 9];
// B fragments in mma.m16n8k16 register order: [tap][ks][n8][lane] -> uint2 {b0,b1}
__device__ uint2 g_bh[9 * 4 * 16 * 32];
__device__ uint2 g_bl[9 * 4 * 16 * 32];

// ---------------- helpers ----------------
__device__ __forceinline__ uint32_t smem_u32(const void* p) {
    uint32_t a;
    asm("{ .reg .u64 t; cvta.to.shared.u64 t, %1; cvt.u32.u64 %0, t; }" : "=r"(a) : "l"(p));
    return a;
}
__device__ __forceinline__ uint32_t cvt_bf16x2(float lo, float hi) {
    uint32_t r;
    asm("cvt.rn.bf16x2.f32 %0, %1, %2;" : "=r"(r) : "f"(hi), "f"(lo));
    return r;
}
__device__ __forceinline__ void ldsm_x4(uint32_t* r, uint32_t addr) {
    asm volatile("ldmatrix.sync.aligned.m8n8.x4.shared.b16 {%0,%1,%2,%3}, [%4];"
                 : "=r"(r[0]), "=r"(r[1]), "=r"(r[2]), "=r"(r[3]) : "r"(addr));
}
__device__ __forceinline__ void mma_bf16(float* d, const uint32_t* a, uint32_t b0, uint32_t b1) {
    asm volatile(
        "mma.sync.aligned.m16n8k16.row.col.f32.bf16.bf16.f32 "
        "{%0,%1,%2,%3}, {%4,%5,%6,%7}, {%8,%9}, {%0,%1,%2,%3};"
        : "+f"(d[0]), "+f"(d[1]), "+f"(d[2]), "+f"(d[3])
        : "r"(a[0]), "r"(a[1]), "r"(a[2]), "r"(a[3]), "r"(b0), "r"(b1));
}

// ---------------- precompute: distortion tables (faithful fp64 — branch signs at
// h=0 depend on fp64 rounding of cos(pi/2); fp32 flips them, see R5 failure) ----------------
__global__ void precompute_kernel() {
    int idx = blockIdx.x * blockDim.x + threadIdx.x;
    if (idx >= H_ * 9) return;
    int h = idx / 9, k = idx % 9;
    const double pi = 3.14159265358979323846;
    double unit_w = 2.0 * pi / (double)W_;
    double unit_h = pi / (2.0 * (double)H_);
    double rho = tan(unit_w);
    double phi = ((double)H_ - (double)h) * unit_h;
    double cphi = cos(phi), sphi = sin(phi);
    const int ra[9] = { 1, 1, 1, 0, 0, 0, -1, -1, -1 };
    const int rb[9] = { -1, 0, 1, -1, 0, 1, -1, 0, 1 };
    double a = (double)ra[k], b = (double)rb[k];
    double ux = cphi + rho * (b * (-sphi * cphi));
    double uy = sphi + rho * (b * (cphi * cphi));
    double uz = rho * (a * (-cphi));

    double bse = atan2(uz, ux);
    double theta_r;
    if (ux > 0.0)      theta_r = bse;
    else if (ux < 0.0) theta_r = (uz >= 0.0) ? (bse + pi) : (bse - pi);
    else               theta_r = (uz > 0.0) ? (0.5 * pi) : (-0.5 * pi);
    double phi_r = asin(uy);
    double x_r = (theta_r / pi + 1.0) * 0.5 * (double)W_;
    double y_r = (1.0 - 2.0 * phi_r / pi) * (double)H_;

    double bse_c = atan2(0.0, cphi);
    double theta_c;
    if (cphi > 0.0)      theta_c = bse_c;
    else if (cphi < 0.0) theta_c = bse_c + pi;
    else                 theta_c = -0.5 * pi;
    double x_rc = (theta_c / pi + 1.0) * 0.5 * (double)W_;
    double y_rc = (1.0 - 2.0 * asin(sphi) / pi) * (double)H_;

    float off_to_y = (float)(x_r - x_rc);   // original's swap: x_r diff -> y
    float off_to_x = (float)(y_r - y_rc);

    int dy = k / 3;
    float yf = (float)(h + dy) + off_to_y;
    yf = fminf(fmaxf(yf, 0.0f), (float)(IH - 1));
    int y0 = (int)floorf(yf);
    int y1 = y0 + 1;
    y0 = max(0, min(y0, IH - 1));
    y1 = max(0, min(y1, IH - 1));
    g_y0t[idx] = y0;
    g_y1t[idx] = y1;
    g_wyT[idx] = (float)y1 - yf;
    g_wyB[idx] = yf - (float)y0;
    g_offx[idx] = off_to_x;
}

// ---------------- precompute: B fragments (hi/lo bf16, mma register order) ----------------
__global__ void bfrag_kernel(const float* __restrict__ wk) {
    int idx = blockIdx.x * blockDim.x + threadIdx.x;
    if (idx >= 9 * 4 * 16 * 32) return;
    int lane = idx & 31;
    int n8 = (idx >> 5) & 15;
    int ks = (idx >> 9) & 3;
    int tap = idx >> 11;
    int g = lane >> 2, tg = lane & 3;
    int n = n8 * 8 + g;
    int kb = ks * 16 + 2 * tg;
    float w0 = wk[(size_t)(tap * 64 + kb) * 128 + n];
    float w1 = wk[(size_t)(tap * 64 + kb + 1) * 128 + n];
    float w2 = wk[(size_t)(tap * 64 + kb + 8) * 128 + n];
    float w3 = wk[(size_t)(tap * 64 + kb + 9) * 128 + n];
    __nv_bfloat16 h0 = __float2bfloat16(w0), h1 = __float2bfloat16(w1);
    __nv_bfloat16 h2 = __float2bfloat16(w2), h3 = __float2bfloat16(w3);
    uint32_t bh0 = ((uint32_t)__bfloat16_as_ushort(h1) << 16) | __bfloat16_as_ushort(h0);
    uint32_t bh1 = ((uint32_t)__bfloat16_as_ushort(h3) << 16) | __bfloat16_as_ushort(h2);
    uint32_t bl0 = cvt_bf16x2(w0 - __bfloat162float(h0), w1 - __bfloat162float(h1));
    uint32_t bl1 = cvt_bf16x2(w2 - __bfloat162float(h2), w3 - __bfloat162float(h3));
    g_bh[idx] = make_uint2(bh0, bh1);
    g_bl[idx] = make_uint2(bl0, bl1);
}

// ---------------- main fused kernel ----------------
// CTA: 128 pixels x 128 F. 8 warps: warp_m (2) x warp_n (4); warp tile 64x32.
// Per tap: param pass (per-pixel corner addrs + weights), coalesced gather
// (16 lanes per pixel), then 4 k16-steps x 3 products of mma.bf16.
__global__ __launch_bounds__(256, 2) void distconv_mma(
    const float* __restrict__ inp,
    const float* __restrict__ bias,
    float* __restrict__ out)
{
    __shared__ __align__(128) unsigned char sA_hi[16384];  // [m:128][8 chunks x16B], swizzled
    __shared__ __align__(128) unsigned char sA_lo[16384];
    __shared__ float4 s_w[128];   // per-pixel bilinear weights (pad corners zeroed)
    __shared__ int4   s_a[128];   // per-pixel corner byte offsets

    const int tid = threadIdx.x;
    const int wid = tid >> 5, lane = tid & 31;
    const int warp_m = wid >> 2, warp_n = wid & 3;
    const int g = lane >> 2, tg = lane & 3;

    const int b = blockIdx.z, h = blockIdx.y;
    const int w0 = blockIdx.x * 128;
    const char* inpC = (const char*)(inp + (size_t)b * (H_ * W_ * C_));

    // gather mapping: 16 lanes per pixel, one 16B chunk each (fully coalesced)
    const int chunk = tid & 15;
    const int pgrp = tid >> 4;
    const int cb = chunk * 16;
    const int chalf = (chunk & 1) * 8;
    const int cpair = chunk >> 1;

    // ldmatrix addressing (A): row = warp_m*64 + mi*16 + (lane&15), khalf = lane>>4
    const uint32_t aHi = smem_u32(sA_hi), aLo = smem_u32(sA_lo);
    const uint32_t rowoff = (uint32_t)(warp_m * 64 + (lane & 15)) * 128;
    const int rlo = lane & 7;
    const int khalf = lane >> 4;

    float acc[4][4][4];
#pragma unroll
    for (int mi = 0; mi < 4; ++mi)
#pragma unroll
        for (int ni = 0; ni < 4; ++ni)
#pragma unroll
            for (int q = 0; q < 4; ++q) acc[mi][ni][q] = 0.f;

    for (int k = 0; k < 9; ++k) {
        // ---- param pass: per-pixel corner offsets + weights for this tap ----
        if (tid < 128) {
            int t9 = h * 9 + k;
            int dxk = k - (k / 3) * 3;
            float x = (float)(w0 + tid + dxk) + g_offx[t9];
            if (x < 0.f) x += (float)IW;
            if (x > (float)(IW - 1)) x -= (float)IW;
            int x0 = (int)floorf(x);
            int x1 = x0 + 1;
            x0 = max(0, min(x0, IW - 1));
            x1 = max(0, min(x1, IW - 1));
            float wxl = (float)x1 - x, wxr = x - (float)x0;
            int y0 = g_y0t[t9], y1 = g_y1t[t9];
            float wyT = g_wyT[t9], wyB = g_wyB[t9];
            bool vy0 = (y0 >= 1) && (y0 <= H_);
            bool vy1 = (y1 >= 1) && (y1 <= H_);
            bool vx0 = (x0 >= 1) && (x0 <= W_);
            bool vx1 = (x1 >= 1) && (x1 <= W_);
            float4 wv;
            int4 av;
            wv.x = (vy0 && vx0) ? wyT * wxl : 0.f;
            wv.y = (vy0 && vx1) ? wyT * wxr : 0.f;
            wv.z = (vy1 && vx0) ? wyB * wxl : 0.f;
            wv.w = (vy1 && vx1) ? wyB * wxr : 0.f;
            av.x = (vy0 && vx0) ? ((y0 - 1) * W_ + (x0 - 1)) * 256 : 0;
            av.y = (vy0 && vx1) ? ((y0 - 1) * W_ + (x1 - 1)) * 256 : 0;
            av.z = (vy1 && vx0) ? ((y1 - 1) * W_ + (x0 - 1)) * 256 : 0;
            av.w = (vy1 && vx1) ? ((y1 - 1) * W_ + (x1 - 1)) * 256 : 0;
            s_w[tid] = wv;
            s_a[tid] = av;
        }
        __syncthreads();   // params ready; also: prior tap's ldmatrix reads done

        // ---- gather: coalesced bilinear blend -> bf16 hi/lo swizzled smem ----
#pragma unroll
        for (int it = 0; it < 8; ++it) {
            int p = it * 16 + pgrp;
            float4 wv = s_w[p];
            int4 av = s_a[p];
            float4 q0 = *(const float4*)(inpC + av.x + cb);
            float4 q1 = *(const float4*)(inpC + av.y + cb);
            float4 q2 = *(const float4*)(inpC + av.z + cb);
            float4 q3 = *(const float4*)(inpC + av.w + cb);
            float v0 = wv.x * q0.x + wv.y * q1.x + wv.z * q2.x + wv.w * q3.x;
            float v1 = wv.x * q0.y + wv.y * q1.y + wv.z * q2.y + wv.w * q3.y;
            float v2 = wv.x * q0.z + wv.y * q1.z + wv.z * q2.z + wv.w * q3.z;
            float v3 = wv.x * q0.w + wv.y * q1.w + wv.z * q2.w + wv.w * q3.w;
            __nv_bfloat16 h0 = __float2bfloat16(v0), h1 = __float2bfloat16(v1);
            __nv_bfloat16 h2 = __float2bfloat16(v2), h3 = __float2bfloat16(v3);
            uint32_t hiA = ((uint32_t)__bfloat16_as_ushort(h1) << 16) | __bfloat16_as_ushort(h0);
            uint32_t hiB = ((uint32_t)__bfloat16_as_ushort(h3) << 16) | __bfloat16_as_ushort(h2);
            uint32_t loA = cvt_bf16x2(v0 - __bfloat162float(h0), v1 - __bfloat162float(h1));
            uint32_t loB = cvt_bf16x2(v2 - __bfloat162float(h2), v3 - __bfloat162float(h3));
            uint32_t addr = (uint32_t)p * 128 + ((uint32_t)(cpair ^ (p & 7)) << 4) + chalf;
            *(uint2*)(sA_hi + addr) = make_uint2(hiA, hiB);
            *(uint2*)(sA_lo + addr) = make_uint2(loA, loB);
        }
        __syncthreads();

        // ---- MMA phase: 4 k16-steps ----
#pragma unroll
        for (int ks = 0; ks < 4; ++ks) {
            uint2 BH[4], BL[4];
            int bidx = ((k * 4 + ks) * 16 + warp_n * 4) * 32 + lane;
#pragma unroll
            for (int ni = 0; ni < 4; ++ni) {
                BH[ni] = g_bh[bidx + ni * 32];
                BL[ni] = g_bl[bidx + ni * 32];
            }
            uint32_t swz = ((uint32_t)((ks * 2 + khalf) ^ rlo)) << 4;
            uint32_t AH[4][4];
#pragma unroll
            for (int mi = 0; mi < 4; ++mi)
                ldsm_x4(AH[mi], aHi + rowoff + (uint32_t)mi * 2048 + swz);
#pragma unroll
            for (int mi = 0; mi < 4; ++mi)
#pragma unroll
                for (int ni = 0; ni < 4; ++ni) {
                    mma_bf16(acc[mi][ni], AH[mi], BH[ni].x, BH[ni].y);
                    mma_bf16(acc[mi][ni], AH[mi], BL[ni].x, BL[ni].y);
                }
            uint32_t AL[4][4];
#pragma unroll
            for (int mi = 0; mi < 4; ++mi)
                ldsm_x4(AL[mi], aLo + rowoff + (uint32_t)mi * 2048 + swz);
#pragma unroll
            for (int mi = 0; mi < 4; ++mi)
#pragma unroll
                for (int ni = 0; ni < 4; ++ni)
                    mma_bf16(acc[mi][ni], AL[mi], BH[ni].x, BH[ni].y);
        }
    }

    // ---- epilogue: bias + relu, float2 stores ----
    float2 bv[4];
#pragma unroll
    for (int ni = 0; ni < 4; ++ni) {
        int f = warp_n * 32 + ni * 8 + 2 * tg;
        bv[ni] = *(const float2*)(bias + f);
    }
    size_t rowbase = (((size_t)b * H_ + h) * W_ + w0) * F_;
#pragma unroll
    for (int mi = 0; mi < 4; ++mi) {
        int mA = warp_m * 64 + mi * 16 + g;
#pragma unroll
        for (int ni = 0; ni < 4; ++ni) {
            int f = warp_n * 32 + ni * 8 + 2 * tg;
            float2 oA, oB;
            oA.x = fmaxf(acc[mi][ni][0] + bv[ni].x, 0.f);
            oA.y = fmaxf(acc[mi][ni][1] + bv[ni].y, 0.f);
            oB.x = fmaxf(acc[mi][ni][2] + bv[ni].x, 0.f);
            oB.y = fmaxf(acc[mi][ni][3] + bv[ni].y, 0.f);
            *(float2*)(out + rowbase + (size_t)mA * F_ + f) = oA;
            *(float2*)(out + rowbase + (size_t)(mA + 8) * F_ + f) = oB;
        }
    }
}

extern "C" void kernel_launch(void* const* d_in, const int* in_sizes, int n_in,
                              void* d_out, int out_size) {
    (void)in_sizes; (void)n_in; (void)out_size;
    const float* inp  = (const float*)d_in[0];
    const float* wk   = (const float*)d_in[1];
    const float* bias = (const float*)d_in[2];
    float* out = (float*)d_out;

    precompute_kernel<<<(H_ * 9 + 127) / 128, 128>>>();
    bfrag_kernel<<<(9 * 4 * 16 * 32 + 255) / 256, 256>>>(wk);
    dim3 grid(W_ / 128, H_, B_);
    distconv_mma<<<grid, 256>>>(inp, bias, out);
}

// round 7
// speedup vs baseline: 3.0395x; 1.2628x over previous
#include <cuda_runtime.h>
#include <cuda_fp16.h>
#include <math.h>
#include <stdint.h>

#define H_ 128
#define W_ 256
#define C_ 64
#define F_ 128
#define B_ 4
#define IH 130
#define IW 258

// ---------------- device scratch ----------------
__device__ int   g_y0t[H_ * 9];
__device__ int   g_y1t[H_ * 9];
__device__ float g_wyT[H_ * 9];
__device__ float g_wyB[H_ * 9];
__device__ float g_offx[H_ * 9];
// B fragments in mma.m16n8k16 register order: [tap][ks][n8][lane] -> uint2 {b0,b1}, fp16
__device__ uint2 g_bh[9 * 4 * 16 * 32];
__device__ uint2 g_bl[9 * 4 * 16 * 32];

// ---------------- helpers ----------------
__device__ __forceinline__ uint32_t smem_u32(const void* p) {
    uint32_t a;
    asm("{ .reg .u64 t; cvta.to.shared.u64 t, %1; cvt.u32.u64 %0, t; }" : "=r"(a) : "l"(p));
    return a;
}
__device__ __forceinline__ uint32_t pack_half2(__half lo, __half hi) {
    return ((uint32_t)__half_as_ushort(hi) << 16) | __half_as_ushort(lo);
}
__device__ __forceinline__ void ldsm_x4(uint32_t* r, uint32_t addr) {
    asm volatile("ldmatrix.sync.aligned.m8n8.x4.shared.b16 {%0,%1,%2,%3}, [%4];"
                 : "=r"(r[0]), "=r"(r[1]), "=r"(r[2]), "=r"(r[3]) : "r"(addr));
}
__device__ __forceinline__ void mma_f16(float* d, const uint32_t* a, uint32_t b0, uint32_t b1) {
    asm volatile(
        "mma.sync.aligned.m16n8k16.row.col.f32.f16.f16.f32 "
        "{%0,%1,%2,%3}, {%4,%5,%6,%7}, {%8,%9}, {%0,%1,%2,%3};"
        : "+f"(d[0]), "+f"(d[1]), "+f"(d[2]), "+f"(d[3])
        : "r"(a[0]), "r"(a[1]), "r"(a[2]), "r"(a[3]), "r"(b0), "r"(b1));
}

// ---------------- combined init: B fragments (blocks 0..71) + distortion tables (block 72) ----
// Tables are computed in fp32 via branch-free analytic forms:
//   theta_r - theta_c = atan(-rho*a / (1 - rho*b*sin(phi)))   [cos(phi)>0 in fp64 semantics,
//       atan2 is scale-invariant in the shared positive factor cos(phi)]
//   phi_r - phi = Taylor series of asin(sin(phi)+delta) - phi, delta = rho*b*cos^2(phi)
// This removes the branch-flip (R5 failure: fp32 cos(pi/2) < 0) and the asin amplification.
__global__ void init_kernel(const float* __restrict__ wk) {
    if (blockIdx.x < 72) {
        int idx = blockIdx.x * 256 + threadIdx.x;   // < 18432
        int lane = idx & 31;
        int n8 = (idx >> 5) & 15;
        int ks = (idx >> 9) & 3;
        int tap = idx >> 11;
        int g = lane >> 2, tg = lane & 3;
        int n = n8 * 8 + g;
        int kb = ks * 16 + 2 * tg;
        float w0 = wk[(size_t)(tap * 64 + kb) * 128 + n];
        float w1 = wk[(size_t)(tap * 64 + kb + 1) * 128 + n];
        float w2 = wk[(size_t)(tap * 64 + kb + 8) * 128 + n];
        float w3 = wk[(size_t)(tap * 64 + kb + 9) * 128 + n];
        __half h0 = __float2half_rn(w0), h1 = __float2half_rn(w1);
        __half h2 = __float2half_rn(w2), h3 = __float2half_rn(w3);
        g_bh[idx] = make_uint2(pack_half2(h0, h1), pack_half2(h2, h3));
        __half l0 = __float2half_rn(w0 - __half2float(h0));
        __half l1 = __float2half_rn(w1 - __half2float(h1));
        __half l2 = __float2half_rn(w2 - __half2float(h2));
        __half l3 = __float2half_rn(w3 - __half2float(h3));
        g_bl[idx] = make_uint2(pack_half2(l0, l1), pack_half2(l2, l3));
        return;
    }
    // ---- distortion tables ----
    for (int idx = threadIdx.x; idx < H_ * 9; idx += 256) {
        int h = idx / 9, k = idx % 9;
        const float pi = 3.14159265358979323846f;
        float unit_w = 2.0f * pi / (float)W_;
        float unit_h = pi / (2.0f * (float)H_);
        float rho = tanf(unit_w);
        float phi = ((float)H_ - (float)h) * unit_h;
        float s = sinf(phi), c = cosf(phi);
        const int ra[9] = { 1, 1, 1, 0, 0, 0, -1, -1, -1 };
        const int rb[9] = { -1, 0, 1, -1, 0, 1, -1, 0, 1 };
        float a = (float)ra[k], b = (float)rb[k];
        // off_to_y = (W/(2*pi)) * atan(t)
        float t = (-rho * a) / (1.0f - rho * b * s);
        float t2 = t * t;
        float at = t * (1.0f - t2 * (1.0f / 3.0f) + t2 * t2 * (1.0f / 5.0f));
        float off_to_y = at * ((float)W_ / (2.0f * pi));
        // off_to_x = -(2H/pi) * eps, eps = asin(s + rho*b*c^2) - phi (series)
        float rb1 = rho * b;
        float eps = rb1 * c * (1.0f
                  + rb1 * s * 0.5f
                  + rb1 * rb1 * (1.0f + 2.0f * s * s) * (1.0f / 6.0f)
                  + rb1 * rb1 * rb1 * s * (9.0f + 6.0f * s * s) * (1.0f / 24.0f));
        float off_to_x = -(2.0f * (float)H_ / pi) * eps;

        int dy = k / 3;
        float yf = (float)(h + dy) + off_to_y;
        yf = fminf(fmaxf(yf, 0.0f), (float)(IH - 1));
        int y0 = (int)floorf(yf);
        int y1 = y0 + 1;
        y0 = max(0, min(y0, IH - 1));
        y1 = max(0, min(y1, IH - 1));
        g_y0t[idx] = y0;
        g_y1t[idx] = y1;
        g_wyT[idx] = (float)y1 - yf;
        g_wyB[idx] = yf - (float)y0;
        g_offx[idx] = off_to_x;
    }
}

// ---------------- main fused kernel ----------------
// CTA: 128 pixels x 128 F. 8 warps: warp_m (2) x warp_n (4); warp tile 64x32.
// Per tap: param pass (per-pixel corner addrs + weights), coalesced gather
// (16 lanes per pixel) -> fp16 A tile, then 4 k16-steps x 2 products (Ah*Bh + Ah*Bl).
__global__ __launch_bounds__(256, 2) void distconv_mma(
    const float* __restrict__ inp,
    const float* __restrict__ bias,
    float* __restrict__ out)
{
    __shared__ __align__(128) unsigned char sA[16384];  // [m:128][8 chunks x16B], swizzled, fp16
    __shared__ float4 s_w[128];   // per-pixel bilinear weights (pad corners zeroed)
    __shared__ int4   s_a[128];   // per-pixel corner byte offsets

    const int tid = threadIdx.x;
    const int wid = tid >> 5, lane = tid & 31;
    const int warp_m = wid >> 2, warp_n = wid & 3;
    const int g = lane >> 2, tg = lane & 3;

    const int b = blockIdx.z, h = blockIdx.y;
    const int w0 = blockIdx.x * 128;
    const char* inpC = (const char*)(inp + (size_t)b * (H_ * W_ * C_));

    // gather mapping: 16 lanes per pixel, one 16B chunk each (fully coalesced)
    const int chunk = tid & 15;
    const int pgrp = tid >> 4;
    const int cb = chunk * 16;
    const int chalf = (chunk & 1) * 8;
    const int cpair = chunk >> 1;

    // ldmatrix addressing (A): row = warp_m*64 + mi*16 + (lane&15), khalf = lane>>4
    const uint32_t aA = smem_u32(sA);
    const uint32_t rowoff = (uint32_t)(warp_m * 64 + (lane & 15)) * 128;
    const int rlo = lane & 7;
    const int khalf = lane >> 4;

    float acc[4][4][4];
#pragma unroll
    for (int mi = 0; mi < 4; ++mi)
#pragma unroll
        for (int ni = 0; ni < 4; ++ni)
#pragma unroll
            for (int q = 0; q < 4; ++q) acc[mi][ni][q] = 0.f;

    for (int k = 0; k < 9; ++k) {
        // ---- param pass: per-pixel corner offsets + weights for this tap ----
        if (tid < 128) {
            int t9 = h * 9 + k;
            int dxk = k - (k / 3) * 3;
            float x = (float)(w0 + tid + dxk) + g_offx[t9];
            if (x < 0.f) x += (float)IW;
            if (x > (float)(IW - 1)) x -= (float)IW;
            int x0 = (int)floorf(x);
            int x1 = x0 + 1;
            x0 = max(0, min(x0, IW - 1));
            x1 = max(0, min(x1, IW - 1));
            float wxl = (float)x1 - x, wxr = x - (float)x0;
            int y0 = g_y0t[t9], y1 = g_y1t[t9];
            float wyT = g_wyT[t9], wyB = g_wyB[t9];
            bool vy0 = (y0 >= 1) && (y0 <= H_);
            bool vy1 = (y1 >= 1) && (y1 <= H_);
            bool vx0 = (x0 >= 1) && (x0 <= W_);
            bool vx1 = (x1 >= 1) && (x1 <= W_);
            float4 wv;
            int4 av;
            wv.x = (vy0 && vx0) ? wyT * wxl : 0.f;
            wv.y = (vy0 && vx1) ? wyT * wxr : 0.f;
            wv.z = (vy1 && vx0) ? wyB * wxl : 0.f;
            wv.w = (vy1 && vx1) ? wyB * wxr : 0.f;
            av.x = (vy0 && vx0) ? ((y0 - 1) * W_ + (x0 - 1)) * 256 : 0;
            av.y = (vy0 && vx1) ? ((y0 - 1) * W_ + (x1 - 1)) * 256 : 0;
            av.z = (vy1 && vx0) ? ((y1 - 1) * W_ + (x0 - 1)) * 256 : 0;
            av.w = (vy1 && vx1) ? ((y1 - 1) * W_ + (x1 - 1)) * 256 : 0;
            s_w[tid] = wv;
            s_a[tid] = av;
        }
        __syncthreads();   // params ready; also: prior tap's ldmatrix reads done

        // ---- gather: coalesced bilinear blend -> fp16 swizzled smem ----
#pragma unroll
        for (int it = 0; it < 8; ++it) {
            int p = it * 16 + pgrp;
            float4 wv = s_w[p];
            int4 av = s_a[p];
            float4 q0 = *(const float4*)(inpC + av.x + cb);
            float4 q1 = *(const float4*)(inpC + av.y + cb);
            float4 q2 = *(const float4*)(inpC + av.z + cb);
            float4 q3 = *(const float4*)(inpC + av.w + cb);
            float v0 = wv.x * q0.x + wv.y * q1.x + wv.z * q2.x + wv.w * q3.x;
            float v1 = wv.x * q0.y + wv.y * q1.y + wv.z * q2.y + wv.w * q3.y;
            float v2 = wv.x * q0.z + wv.y * q1.z + wv.z * q2.z + wv.w * q3.z;
            float v3 = wv.x * q0.w + wv.y * q1.w + wv.z * q2.w + wv.w * q3.w;
            __half2 hA = __floats2half2_rn(v0, v1);
            __half2 hB = __floats2half2_rn(v2, v3);
            uint32_t addr = (uint32_t)p * 128 + ((uint32_t)(cpair ^ (p & 7)) << 4) + chalf;
            *(uint2*)(sA + addr) = make_uint2(*(uint32_t*)&hA, *(uint32_t*)&hB);
        }
        __syncthreads();

        // ---- MMA phase: 4 k16-steps x 2 products ----
#pragma unroll
        for (int ks = 0; ks < 4; ++ks) {
            uint2 BH[4], BL[4];
            int bidx = ((k * 4 + ks) * 16 + warp_n * 4) * 32 + lane;
#pragma unroll
            for (int ni = 0; ni < 4; ++ni) {
                BH[ni] = g_bh[bidx + ni * 32];
                BL[ni] = g_bl[bidx + ni * 32];
            }
            uint32_t swz = ((uint32_t)((ks * 2 + khalf) ^ rlo)) << 4;
            uint32_t AH[4][4];
#pragma unroll
            for (int mi = 0; mi < 4; ++mi)
                ldsm_x4(AH[mi], aA + rowoff + (uint32_t)mi * 2048 + swz);
#pragma unroll
            for (int mi = 0; mi < 4; ++mi)
#pragma unroll
                for (int ni = 0; ni < 4; ++ni) {
                    mma_f16(acc[mi][ni], AH[mi], BH[ni].x, BH[ni].y);
                    mma_f16(acc[mi][ni], AH[mi], BL[ni].x, BL[ni].y);
                }
        }
    }

    // ---- epilogue: bias + relu, float2 stores ----
    float2 bv[4];
#pragma unroll
    for (int ni = 0; ni < 4; ++ni) {
        int f = warp_n * 32 + ni * 8 + 2 * tg;
        bv[ni] = *(const float2*)(bias + f);
    }
    size_t rowbase = (((size_t)b * H_ + h) * W_ + w0) * F_;
#pragma unroll
    for (int mi = 0; mi < 4; ++mi) {
        int mA = warp_m * 64 + mi * 16 + g;
#pragma unroll
        for (int ni = 0; ni < 4; ++ni) {
            int f = warp_n * 32 + ni * 8 + 2 * tg;
            float2 oA, oB;
            oA.x = fmaxf(acc[mi][ni][0] + bv[ni].x, 0.f);
            oA.y = fmaxf(acc[mi][ni][1] + bv[ni].y, 0.f);
            oB.x = fmaxf(acc[mi][ni][2] + bv[ni].x, 0.f);
            oB.y = fmaxf(acc[mi][ni][3] + bv[ni].y, 0.f);
            *(float2*)(out + rowbase + (size_t)mA * F_ + f) = oA;
            *(float2*)(out + rowbase + (size_t)(mA + 8) * F_ + f) = oB;
        }
    }
}

extern "C" void kernel_launch(void* const* d_in, const int* in_sizes, int n_in,
                              void* d_out, int out_size) {
    (void)in_sizes; (void)n_in; (void)out_size;
    const float* inp  = (const float*)d_in[0];
    const float* wk   = (const float*)d_in[1];
    const float* bias = (const float*)d_in[2];
    float* out = (float*)d_out;

    init_kernel<<<73, 256>>>(wk);
    dim3 grid(W_ / 128, H_, B_);
    distconv_mma<<<grid, 256>>>(inp, bias, out);
}

// round 8
// speedup vs baseline: 3.2313x; 1.0631x over previous
#include <cuda_runtime.h>
#include <cuda_fp16.h>
#include <math.h>
#include <stdint.h>

#define H_ 128
#define W_ 256
#define C_ 64
#define F_ 128
#define B_ 4
#define IH 130
#define IW 258

// ---------------- device scratch ----------------
__device__ int   g_y0t[H_ * 9];
__device__ int   g_y1t[H_ * 9];
__device__ float g_wyT[H_ * 9];
__device__ float g_wyB[H_ * 9];
__device__ float g_offx[H_ * 9];
// B fragments in mma.m16n8k16 register order: [tap][ks][n8][lane] -> uint2 {b0,b1}, fp16
__device__ uint2 g_bh[9 * 4 * 16 * 32];
__device__ uint2 g_bl[9 * 4 * 16 * 32];

// ---------------- helpers ----------------
__device__ __forceinline__ uint32_t smem_u32(const void* p) {
    uint32_t a;
    asm("{ .reg .u64 t; cvta.to.shared.u64 t, %1; cvt.u32.u64 %0, t; }" : "=r"(a) : "l"(p));
    return a;
}
__device__ __forceinline__ uint32_t pack_half2(__half lo, __half hi) {
    return ((uint32_t)__half_as_ushort(hi) << 16) | __half_as_ushort(lo);
}
__device__ __forceinline__ void ldsm_x4(uint32_t* r, uint32_t addr) {
    asm volatile("ldmatrix.sync.aligned.m8n8.x4.shared.b16 {%0,%1,%2,%3}, [%4];"
                 : "=r"(r[0]), "=r"(r[1]), "=r"(r[2]), "=r"(r[3]) : "r"(addr));
}
__device__ __forceinline__ void mma_f16(float* d, const uint32_t* a, uint32_t b0, uint32_t b1) {
    asm volatile(
        "mma.sync.aligned.m16n8k16.row.col.f32.f16.f16.f32 "
        "{%0,%1,%2,%3}, {%4,%5,%6,%7}, {%8,%9}, {%0,%1,%2,%3};"
        : "+f"(d[0]), "+f"(d[1]), "+f"(d[2]), "+f"(d[3])
        : "r"(a[0]), "r"(a[1]), "r"(a[2]), "r"(a[3]), "r"(b0), "r"(b1));
}

// ---------------- combined init: B fragments (blocks 0..71) + distortion tables (block 72) ----
__global__ void init_kernel(const float* __restrict__ wk) {
    if (blockIdx.x < 72) {
        int idx = blockIdx.x * 256 + threadIdx.x;   // < 18432
        int lane = idx & 31;
        int n8 = (idx >> 5) & 15;
        int ks = (idx >> 9) & 3;
        int tap = idx >> 11;
        int g = lane >> 2, tg = lane & 3;
        int n = n8 * 8 + g;
        int kb = ks * 16 + 2 * tg;
        float w0 = wk[(size_t)(tap * 64 + kb) * 128 + n];
        float w1 = wk[(size_t)(tap * 64 + kb + 1) * 128 + n];
        float w2 = wk[(size_t)(tap * 64 + kb + 8) * 128 + n];
        float w3 = wk[(size_t)(tap * 64 + kb + 9) * 128 + n];
        __half h0 = __float2half_rn(w0), h1 = __float2half_rn(w1);
        __half h2 = __float2half_rn(w2), h3 = __float2half_rn(w3);
        g_bh[idx] = make_uint2(pack_half2(h0, h1), pack_half2(h2, h3));
        __half l0 = __float2half_rn(w0 - __half2float(h0));
        __half l1 = __float2half_rn(w1 - __half2float(h1));
        __half l2 = __float2half_rn(w2 - __half2float(h2));
        __half l3 = __float2half_rn(w3 - __half2float(h3));
        g_bl[idx] = make_uint2(pack_half2(l0, l1), pack_half2(l2, l3));
        return;
    }
    // ---- distortion tables (branch-free analytic fp32, see R7) ----
    for (int idx = threadIdx.x; idx < H_ * 9; idx += 256) {
        int h = idx / 9, k = idx % 9;
        const float pi = 3.14159265358979323846f;
        float unit_w = 2.0f * pi / (float)W_;
        float unit_h = pi / (2.0f * (float)H_);
        float rho = tanf(unit_w);
        float phi = ((float)H_ - (float)h) * unit_h;
        float s = sinf(phi), c = cosf(phi);
        const int ra[9] = { 1, 1, 1, 0, 0, 0, -1, -1, -1 };
        const int rb[9] = { -1, 0, 1, -1, 0, 1, -1, 0, 1 };
        float a = (float)ra[k], b = (float)rb[k];
        float t = (-rho * a) / (1.0f - rho * b * s);
        float t2 = t * t;
        float at = t * (1.0f - t2 * (1.0f / 3.0f) + t2 * t2 * (1.0f / 5.0f));
        float off_to_y = at * ((float)W_ / (2.0f * pi));
        float rb1 = rho * b;
        float eps = rb1 * c * (1.0f
                  + rb1 * s * 0.5f
                  + rb1 * rb1 * (1.0f + 2.0f * s * s) * (1.0f / 6.0f)
                  + rb1 * rb1 * rb1 * s * (9.0f + 6.0f * s * s) * (1.0f / 24.0f));
        float off_to_x = -(2.0f * (float)H_ / pi) * eps;

        int dy = k / 3;
        float yf = (float)(h + dy) + off_to_y;
        yf = fminf(fmaxf(yf, 0.0f), (float)(IH - 1));
        int y0 = (int)floorf(yf);
        int y1 = y0 + 1;
        y0 = max(0, min(y0, IH - 1));
        y1 = max(0, min(y1, IH - 1));
        g_y0t[idx] = y0;
        g_y1t[idx] = y1;
        g_wyT[idx] = (float)y1 - yf;
        g_wyB[idx] = yf - (float)y0;
        g_offx[idx] = off_to_x;
    }
}

// ---------------- main fused kernel ----------------
// CTA: 128 pixels x 128 F. 8 warps: warp_m (2) x warp_n (4); warp tile 64x32.
// Software pipelined across taps: double-buffered A tile + params, ONE sync per tap.
//   iter k: gather A[k&1] (params P[k&1] ready), compute P[(k+1)&1], sync, MMA from A[k&1].
// MMA(k) readers of A[k&1] are protected from gather(k+1) writers of A[(k+1)&1] by
// buffer disjointness; write->read edges are protected by the single barrier.
__global__ __launch_bounds__(256, 2) void distconv_mma(
    const float* __restrict__ inp,
    const float* __restrict__ bias,
    float* __restrict__ out)
{
    __shared__ __align__(128) unsigned char sA[2][16384];  // [m:128][8 chunks x16B], swizzled, fp16
    __shared__ float4 s_w[2][128];   // per-pixel bilinear weights (pad corners zeroed)
    __shared__ int4   s_a[2][128];   // per-pixel corner byte offsets

    const int tid = threadIdx.x;
    const int wid = tid >> 5, lane = tid & 31;
    const int warp_m = wid >> 2, warp_n = wid & 3;
    const int g = lane >> 2, tg = lane & 3;

    const int b = blockIdx.z, h = blockIdx.y;
    const int w0 = blockIdx.x * 128;
    const char* inpC = (const char*)(inp + (size_t)b * (H_ * W_ * C_));

    // gather mapping: 16 lanes per pixel, one 16B chunk each (fully coalesced)
    const int chunk = tid & 15;
    const int pgrp = tid >> 4;
    const int cb = chunk * 16;
    const int chalf = (chunk & 1) * 8;
    const int cpair = chunk >> 1;

    // ldmatrix addressing (A): row = warp_m*64 + mi*16 + (lane&15), khalf = lane>>4
    const uint32_t aA0 = smem_u32(sA[0]), aA1 = smem_u32(sA[1]);
    const uint32_t rowoff = (uint32_t)(warp_m * 64 + (lane & 15)) * 128;
    const int rlo = lane & 7;
    const int khalf = lane >> 4;

    float acc[4][4][4];
#pragma unroll
    for (int mi = 0; mi < 4; ++mi)
#pragma unroll
        for (int ni = 0; ni < 4; ++ni)
#pragma unroll
            for (int q = 0; q < 4; ++q) acc[mi][ni][q] = 0.f;

    // ---- param computation for one tap into buffer bb ----
    auto compute_params = [&](int k, int bb) {
        if (tid < 128) {
            int t9 = h * 9 + k;
            int dxk = k - (k / 3) * 3;
            float x = (float)(w0 + tid + dxk) + g_offx[t9];
            if (x < 0.f) x += (float)IW;
            if (x > (float)(IW - 1)) x -= (float)IW;
            int x0 = (int)floorf(x);
            int x1 = x0 + 1;
            x0 = max(0, min(x0, IW - 1));
            x1 = max(0, min(x1, IW - 1));
            float wxl = (float)x1 - x, wxr = x - (float)x0;
            int y0 = g_y0t[t9], y1 = g_y1t[t9];
            float wyT = g_wyT[t9], wyB = g_wyB[t9];
            bool vy0 = (y0 >= 1) && (y0 <= H_);
            bool vy1 = (y1 >= 1) && (y1 <= H_);
            bool vx0 = (x0 >= 1) && (x0 <= W_);
            bool vx1 = (x1 >= 1) && (x1 <= W_);
            float4 wv;
            int4 av;
            wv.x = (vy0 && vx0) ? wyT * wxl : 0.f;
            wv.y = (vy0 && vx1) ? wyT * wxr : 0.f;
            wv.z = (vy1 && vx0) ? wyB * wxl : 0.f;
            wv.w = (vy1 && vx1) ? wyB * wxr : 0.f;
            av.x = (vy0 && vx0) ? ((y0 - 1) * W_ + (x0 - 1)) * 256 : 0;
            av.y = (vy0 && vx1) ? ((y0 - 1) * W_ + (x1 - 1)) * 256 : 0;
            av.z = (vy1 && vx0) ? ((y1 - 1) * W_ + (x0 - 1)) * 256 : 0;
            av.w = (vy1 && vx1) ? ((y1 - 1) * W_ + (x1 - 1)) * 256 : 0;
            s_w[bb][tid] = wv;
            s_a[bb][tid] = av;
        }
    };

    // prologue: params for tap 0
    compute_params(0, 0);
    __syncthreads();

    for (int k = 0; k < 9; ++k) {
        const int cur = k & 1;
        // ---- gather: coalesced bilinear blend -> fp16 swizzled smem (buffer cur) ----
        unsigned char* sAc = sA[cur];
#pragma unroll
        for (int it = 0; it < 8; ++it) {
            int p = it * 16 + pgrp;
            float4 wv = s_w[cur][p];
            int4 av = s_a[cur][p];
            float4 q0 = *(const float4*)(inpC + av.x + cb);
            float4 q1 = *(const float4*)(inpC + av.y + cb);
            float4 q2 = *(const float4*)(inpC + av.z + cb);
            float4 q3 = *(const float4*)(inpC + av.w + cb);
            float v0 = wv.x * q0.x + wv.y * q1.x + wv.z * q2.x + wv.w * q3.x;
            float v1 = wv.x * q0.y + wv.y * q1.y + wv.z * q2.y + wv.w * q3.y;
            float v2 = wv.x * q0.z + wv.y * q1.z + wv.z * q2.z + wv.w * q3.z;
            float v3 = wv.x * q0.w + wv.y * q1.w + wv.z * q2.w + wv.w * q3.w;
            __half2 hA = __floats2half2_rn(v0, v1);
            __half2 hB = __floats2half2_rn(v2, v3);
            uint32_t addr = (uint32_t)p * 128 + ((uint32_t)(cpair ^ (p & 7)) << 4) + chalf;
            *(uint2*)(sAc + addr) = make_uint2(*(uint32_t*)&hA, *(uint32_t*)&hB);
        }
        // ---- params for next tap (other buffer) ----
        if (k < 8) compute_params(k + 1, cur ^ 1);
        __syncthreads();   // A[cur] + P[next] visible to all

        // ---- MMA phase: 4 k16-steps x 2 products; no trailing sync (pipelined) ----
        const uint32_t aA = cur ? aA1 : aA0;
#pragma unroll
        for (int ks = 0; ks < 4; ++ks) {
            uint2 BH[4], BL[4];
            int bidx = ((k * 4 + ks) * 16 + warp_n * 4) * 32 + lane;
#pragma unroll
            for (int ni = 0; ni < 4; ++ni) {
                BH[ni] = g_bh[bidx + ni * 32];
                BL[ni] = g_bl[bidx + ni * 32];
            }
            uint32_t swz = ((uint32_t)((ks * 2 + khalf) ^ rlo)) << 4;
            uint32_t AH[4][4];
#pragma unroll
            for (int mi = 0; mi < 4; ++mi)
                ldsm_x4(AH[mi], aA + rowoff + (uint32_t)mi * 2048 + swz);
#pragma unroll
            for (int mi = 0; mi < 4; ++mi)
#pragma unroll
                for (int ni = 0; ni < 4; ++ni) {
                    mma_f16(acc[mi][ni], AH[mi], BH[ni].x, BH[ni].y);
                    mma_f16(acc[mi][ni], AH[mi], BL[ni].x, BL[ni].y);
                }
        }
    }

    // ---- epilogue: bias + relu, float2 stores ----
    float2 bv[4];
#pragma unroll
    for (int ni = 0; ni < 4; ++ni) {
        int f = warp_n * 32 + ni * 8 + 2 * tg;
        bv[ni] = *(const float2*)(bias + f);
    }
    size_t rowbase = (((size_t)b * H_ + h) * W_ + w0) * F_;
#pragma unroll
    for (int mi = 0; mi < 4; ++mi) {
        int mA = warp_m * 64 + mi * 16 + g;
#pragma unroll
        for (int ni = 0; ni < 4; ++ni) {
            int f = warp_n * 32 + ni * 8 + 2 * tg;
            float2 oA, oB;
            oA.x = fmaxf(acc[mi][ni][0] + bv[ni].x, 0.f);
            oA.y = fmaxf(acc[mi][ni][1] + bv[ni].y, 0.f);
            oB.x = fmaxf(acc[mi][ni][2] + bv[ni].x, 0.f);
            oB.y = fmaxf(acc[mi][ni][3] + bv[ni].y, 0.f);
            *(float2*)(out + rowbase + (size_t)mA * F_ + f) = oA;
            *(float2*)(out + rowbase + (size_t)(mA + 8) * F_ + f) = oB;
        }
    }
}

extern "C" void kernel_launch(void* const* d_in, const int* in_sizes, int n_in,
                              void* d_out, int out_size) {
    (void)in_sizes; (void)n_in; (void)out_size;
    const float* inp  = (const float*)d_in[0];
    const float* wk   = (const float*)d_in[1];
    const float* bias = (const float*)d_in[2];
    float* out = (float*)d_out;

    init_kernel<<<73, 256>>>(wk);
    dim3 grid(W_ / 128, H_, B_);
    distconv_mma<<<grid, 256>>>(inp, bias, out);
}